// round 16
// baseline (speedup 1.0000x reference)
#include <cuda_runtime.h>
#include <cuda_bf16.h>
#include <cstdint>

#define TOPK     5
#define ROWS     112                 // rows per CTA -> grid 147
#define NP       100
#define NPP      104                 // padded points = 13 n8-tiles
#define NTILES   13
#define NTHREADS 448                 // 14 warps: 7 m-bands x 2 k-splits
#define MARGIN   4.0f                // > 2x worst-case bf16 dot error (~1.72)
#define CANDCAP  32
#define SCSTR    106                 // scores row stride (floats, even, bank-spread)

// ---- SMEM layout (bytes) ----
#define XH_OFF   0                          // x_hi  bf16 [112][256] swizzled : 57344
#define RH_OFF   57344                      // ref_hi bf16 [104][256] swizzled: 53248
#define SC_OFF   (57344 + 53248)            // scores f32 [112][106]          : 47488
#define RN_OFF   (SC_OFF + 47488)           // rn f32 [104]                   : 416
#define CN_OFF   (RN_OFF + 416)             // cnt int [112]                  : 448
#define CD_OFF   (CN_OFF + 448)             // cand int [112][32]             : 14336
#define SMEM_BYTES (CD_OFF + 14336)         // 173,280
// merge buffers reuse the scores region after candidates are built:
#define MF_OFF   SC_OFF                     // float [3][112][5]
#define MI_OFF   (SC_OFF + 3 * 112 * TOPK * 4)

__device__ __forceinline__ uint32_t lds32(uint32_t a) {
    uint32_t v; asm volatile("ld.shared.b32 %0,[%1];" : "=r"(v) : "r"(a)); return v;
}
__device__ __forceinline__ float2 lds_f2(uint32_t a) {
    float2 v; asm volatile("ld.shared.v2.f32 {%0,%1},[%2];" : "=f"(v.x), "=f"(v.y) : "r"(a)); return v;
}
__device__ __forceinline__ void sts_f2(uint32_t a, float2 v) {
    asm volatile("st.shared.v2.f32 [%0],{%1,%2};" :: "r"(a), "f"(v.x), "f"(v.y) : "memory");
}
__device__ __forceinline__ uint32_t pack_bf2(float a, float b) {
    __nv_bfloat162 h = __floats2bfloat162_rn(a, b);     // h.x = a (low), h.y = b (high)
    return *reinterpret_cast<uint32_t*>(&h);
}
// swizzled bf16 tile address: row stride 512B, 16B chunks XOR (row&7)
__device__ __forceinline__ uint32_t bf_addr(uint32_t base, int r, int kb) {
    return base + (uint32_t)(r * 512) + ((uint32_t)(((kb >> 4) ^ (r & 7)) << 4)) + (uint32_t)(kb & 15);
}

__device__ __forceinline__ void mma16816(float* c, uint32_t a0, uint32_t a1,
                                         uint32_t a2, uint32_t a3, uint32_t b0, uint32_t b1) {
    asm volatile(
        "mma.sync.aligned.m16n8k16.row.col.f32.bf16.bf16.f32 "
        "{%0,%1,%2,%3}, {%4,%5,%6,%7}, {%8,%9}, {%0,%1,%2,%3};"
        : "+f"(c[0]), "+f"(c[1]), "+f"(c[2]), "+f"(c[3])
        : "r"(a0), "r"(a1), "r"(a2), "r"(a3), "r"(b0), "r"(b1));
}

// lex (dist, idx) insert — exact lax.top_k semantics, order-independent
__device__ __forceinline__ void lex_insert(float d, int p, float* ed, int* ei) {
    if (d < ed[TOPK - 1] || (d == ed[TOPK - 1] && p < ei[TOPK - 1])) {
        ed[TOPK - 1] = d; ei[TOPK - 1] = p;
#pragma unroll
        for (int t = TOPK - 1; t >= 1; --t) {
            if (ed[t] < ed[t - 1] || (ed[t] == ed[t - 1] && ei[t] < ei[t - 1])) {
                float tf = ed[t]; ed[t] = ed[t - 1]; ed[t - 1] = tf;
                int   ti = ei[t]; ei[t] = ei[t - 1]; ei[t - 1] = ti;
            }
        }
    }
}

__global__ void __launch_bounds__(NTHREADS)
knn_topk_kernel(const float* __restrict__ x,
                const float* __restrict__ ref,
                float* __restrict__ out,     // indices as float32 (__output__ dtype!)
                int B)
{
    extern __shared__ unsigned char smem[];
    const uint32_t s0 = (uint32_t)__cvta_generic_to_shared(smem);

    const int tid  = threadIdx.x;
    const int row0 = blockIdx.x * ROWS;
    const int nrows = (B - row0) < ROWS ? (B - row0) : ROWS;

    // ---------- Phase 0: fill bf16 tiles (swizzled), rn ----------
    {   // x_hi: rows >= nrows zero-filled
        const float4* x4 = (const float4*)x;
        for (int i = tid; i < ROWS * 64; i += NTHREADS) {
            int r = i >> 6, c4 = i & 63;
            float4 v = make_float4(0.f, 0.f, 0.f, 0.f);
            if (r < nrows) v = x4[(size_t)(row0 + r) * 64 + c4];
            uint2 u; u.x = pack_bf2(v.x, v.y); u.y = pack_bf2(v.z, v.w);
            uint32_t a = bf_addr(s0 + XH_OFF, r, c4 * 8);
            asm volatile("st.shared.v2.b32 [%0],{%1,%2};" :: "r"(a), "r"(u.x), "r"(u.y) : "memory");
        }
        const float4* r4 = (const float4*)ref;
        for (int i = tid; i < NPP * 64; i += NTHREADS) {
            int p = i >> 6, c4 = i & 63;
            float4 v = make_float4(0.f, 0.f, 0.f, 0.f);
            if (p < NP) v = r4[(size_t)p * 64 + c4];
            uint2 u; u.x = pack_bf2(v.x, v.y); u.y = pack_bf2(v.z, v.w);
            uint32_t a = bf_addr(s0 + RH_OFF, p, c4 * 8);
            asm volatile("st.shared.v2.b32 [%0],{%1,%2};" :: "r"(a), "r"(u.x), "r"(u.y) : "memory");
        }
        if (tid < NPP) {
            float rn = 1e30f;
            if (tid < NP) {
                const float4* rr = (const float4*)ref + (size_t)tid * 64;
                float a0 = 0.f, a1 = 0.f, a2 = 0.f, a3 = 0.f;
                for (int j = 0; j < 64; ++j) {
                    float4 v = rr[j];
                    a0 = fmaf(v.x, v.x, a0); a1 = fmaf(v.y, v.y, a1);
                    a2 = fmaf(v.z, v.z, a2); a3 = fmaf(v.w, v.w, a3);
                }
                rn = (a0 + a1) + (a2 + a3);
            }
            *(float*)(smem + RN_OFF + tid * 4) = rn;
        }
    }
    __syncthreads();

    // ---------- Phase 1: HMMA GEMM, scores = rn - 2*dot ----------
    const int wid = tid >> 5, lane = tid & 31;
    const int g = lane >> 2, tg = lane & 3;
    const int mb = wid >> 1, ks = wid & 1;      // 7 m-bands x 2 k-splits
    const int mr = mb * 16;

    float C[NTILES][4];
#pragma unroll
    for (int nt = 0; nt < NTILES; ++nt)
#pragma unroll
        for (int k = 0; k < 4; ++k) C[nt][k] = 0.f;

    for (int k16 = ks * 8; k16 < ks * 8 + 8; ++k16) {
        int kb = k16 * 32 + tg * 4;
        uint32_t a0 = lds32(bf_addr(s0 + XH_OFF, mr + g,     kb));
        uint32_t a1 = lds32(bf_addr(s0 + XH_OFF, mr + g + 8, kb));
        uint32_t a2 = lds32(bf_addr(s0 + XH_OFF, mr + g,     kb + 16));
        uint32_t a3 = lds32(bf_addr(s0 + XH_OFF, mr + g + 8, kb + 16));
#pragma unroll
        for (int nt = 0; nt < NTILES; ++nt) {
            int n = nt * 8 + g;
            uint32_t b0 = lds32(bf_addr(s0 + RH_OFF, n, kb));
            uint32_t b1 = lds32(bf_addr(s0 + RH_OFF, n, kb + 16));
            mma16816(C[nt], a0, a1, a2, a3, b0, b1);
        }
    }

    // ks=0 warps: scores = rn - 2*dot_lo
    const float* rn = (const float*)(smem + RN_OFF);
    if (ks == 0) {
#pragma unroll
        for (int nt = 0; nt < NTILES; ++nt) {
            int n0 = nt * 8 + tg * 2;
            uint32_t aL = s0 + SC_OFF + (uint32_t)(((mr + g) * SCSTR + n0) * 4);
            uint32_t aH = s0 + SC_OFF + (uint32_t)(((mr + g + 8) * SCSTR + n0) * 4);
            sts_f2(aL, make_float2(fmaf(-2.f, C[nt][0], rn[n0]),
                                   fmaf(-2.f, C[nt][1], rn[n0 + 1])));
            sts_f2(aH, make_float2(fmaf(-2.f, C[nt][2], rn[n0]),
                                   fmaf(-2.f, C[nt][3], rn[n0 + 1])));
        }
    }
    __syncthreads();
    if (ks == 1) {                              // scores -= 2*dot_hi
#pragma unroll
        for (int nt = 0; nt < NTILES; ++nt) {
            int n0 = nt * 8 + tg * 2;
            uint32_t aL = s0 + SC_OFF + (uint32_t)(((mr + g) * SCSTR + n0) * 4);
            uint32_t aH = s0 + SC_OFF + (uint32_t)(((mr + g + 8) * SCSTR + n0) * 4);
            float2 vL = lds_f2(aL), vH = lds_f2(aH);
            vL.x = fmaf(-2.f, C[nt][0], vL.x); vL.y = fmaf(-2.f, C[nt][1], vL.y);
            vH.x = fmaf(-2.f, C[nt][2], vH.x); vH.y = fmaf(-2.f, C[nt][3], vH.y);
            sts_f2(aL, vL); sts_f2(aH, vH);
        }
    }
    __syncthreads();

    // ---------- Phase 2: per-row tau + candidate list ----------
    if (tid < ROWS) {
        const float* sc = (const float*)(smem + SC_OFF) + tid * SCSTR;
        float bd[TOPK];
#pragma unroll
        for (int k = 0; k < TOPK; ++k) bd[k] = 1e38f;
        for (int p = 0; p < NPP; ++p) {
            float s = sc[p];
            if (s < bd[TOPK - 1]) {
                bd[TOPK - 1] = s;
#pragma unroll
                for (int t = TOPK - 1; t >= 1; --t)
                    if (bd[t] < bd[t - 1]) { float tf = bd[t]; bd[t] = bd[t - 1]; bd[t - 1] = tf; }
            }
        }
        float tau = bd[TOPK - 1] + MARGIN;
        int* cand = (int*)(smem + CD_OFF) + tid * CANDCAP;
        int cnt = 0;
        for (int p = 0; p < NP; ++p) {
            if (sc[p] <= tau) { if (cnt < CANDCAP) cand[cnt] = p; ++cnt; }
        }
        *(int*)(smem + CN_OFF + tid * 4) = cnt;
    }
    __syncthreads();

    // ---------- Phase 3: exact fp32 rescore (from GMEM, proven R4 tree) ----------
    const int r = tid >> 2, q = tid & 3;
    const float INF = __int_as_float(0x7f800000);
    float ed[TOPK]; int ei[TOPK];
#pragma unroll
    for (int k = 0; k < TOPK; ++k) { ed[k] = INF; ei[k] = 0x7fffffff; }

    if (r < nrows) {
        int cnt = *(int*)(smem + CN_OFF + r * 4);
        const int* cand = (const int*)(smem + CD_OFF) + r * CANDCAP;
        int n_eff = (cnt <= CANDCAP) ? cnt : NP;    // overflow -> rescore all (always correct)
        const float4* xr = (const float4*)x + (size_t)(row0 + r) * 64;
        for (int s = q; s < n_eff; s += 4) {
            int p = (cnt <= CANDCAP) ? cand[s] : s;
            const float4* rr = (const float4*)ref + (size_t)p * 64;
            float a0 = 0.f, a1 = 0.f, a2 = 0.f, a3 = 0.f;
#pragma unroll 4
            for (int j = 0; j < 64; ++j) {
                float4 xv = xr[j]; float4 rv = rr[j];
                float d0 = xv.x - rv.x, d1 = xv.y - rv.y;
                float d2 = xv.z - rv.z, d3 = xv.w - rv.w;
                a0 = fmaf(d0, d0, a0); a1 = fmaf(d1, d1, a1);
                a2 = fmaf(d2, d2, a2); a3 = fmaf(d3, d3, a3);
            }
            lex_insert((a0 + a1) + (a2 + a3), p, ed, ei);
        }
    }

    // ---------- Phase 4: merge 4 slots per row (reuse scores region) ----------
    float* mf = (float*)(smem + MF_OFF);
    int*   mi = (int*)(smem + MI_OFF);
    if (q >= 1) {
        int base = ((q - 1) * ROWS + r) * TOPK;
#pragma unroll
        for (int k = 0; k < TOPK; ++k) { mf[base + k] = ed[k]; mi[base + k] = ei[k]; }
    }
    __syncthreads();
    if (q == 0 && r < nrows) {
        for (int qq = 1; qq < 4; ++qq) {
            int base = ((qq - 1) * ROWS + r) * TOPK;
#pragma unroll
            for (int k = 0; k < TOPK; ++k)
                lex_insert(mf[base + k], mi[base + k], ed, ei);
        }
        float* o = out + (size_t)(row0 + r) * TOPK;
#pragma unroll
        for (int k = 0; k < TOPK; ++k) o[k] = (float)ei[k];
    }
}

extern "C" void kernel_launch(void* const* d_in, const int* in_sizes, int n_in,
                              void* d_out, int out_size)
{
    const float* a = (const float*)d_in[0];
    const float* b = (const float*)d_in[1];
    const float* x   = (in_sizes[0] >= in_sizes[1]) ? a : b;
    const float* ref = (in_sizes[0] >= in_sizes[1]) ? b : a;
    int B = out_size / TOPK;                     // 16384

    float* out = (float*)d_out;
    cudaFuncSetAttribute(knn_topk_kernel,
                         cudaFuncAttributeMaxDynamicSharedMemorySize, SMEM_BYTES);
    int grid = (B + ROWS - 1) / ROWS;            // 147
    knn_topk_kernel<<<grid, NTHREADS, SMEM_BYTES>>>(x, ref, out, B);
}